// round 8
// baseline (speedup 1.0000x reference)
#include <cuda_runtime.h>

#define PH   8
#define NN   8
#define KK   64
#define CC   128
#define HH   128
#define WW   128
#define HW   (HH * WW)

#define CPB   8                  // channels per block
#define TPB   512

// One block: one (n,k) box, BOTH directions d=0/1, CPB channels.
// Threads [0, nv): one dense valid (i,j) each; record computed once.
//   Phase A: gather ALL channels into v[0..7] (32 independent LDGs in flight).
//   Phase B: store all (16 coalesced STG.32 across the two planes).
// Threads [nv, TPB): zero-fill the padding region (identical in both planes).

__global__ void __launch_bounds__(TPB)
bbp_kernel(const float* __restrict__ x,
           const float* __restrict__ boxes,
           float* __restrict__ feats,
           float* __restrict__ widths,
           int MW)
{
    const int nk  = blockIdx.x;            // n*KK + k
    const int n   = nk >> 6;
    const int cc0 = blockIdx.y * CPB;
    const int tid = threadIdx.x;

    // ---- box parameters (uniform per block) ----
    const float4 b = reinterpret_cast<const float4*>(boxes)[nk];
    const float xmin = b.x, ymin = b.y, xmax = b.z, ymax = b.w;
    const bool valid_box = !(xmin == 0.f && ymin == 0.f && xmax == 0.f && ymax == 0.f);
    const float bwf = valid_box ? (xmax - xmin) : 1.f;
    const float bhf = valid_box ? (ymax - ymin) : 1.f;
    const bool wide = bwf > bhf;
    const float ratio = wide ? (bwf / bhf) : (bhf / bwf);
    const int   width = valid_box ? (int)ceilf(ratio * (float)PH) : 0;
    const float wf    = (float)(width > 2 ? width : 2);
    const float inv_wf1 = 1.0f / (wf - 1.0f);
    const float inv_ph1 = 1.0f / (float)(PH - 1);

    const int nij = PH * MW;
    const int nv  = PH * width;            // dense valid count (<= 512)

    if (tid == 0 && blockIdx.y == 0) {
        widths[(size_t)nk * 2 + 0] = (float)width;
        widths[(size_t)nk * 2 + 1] = (float)width;
    }

    const float* __restrict__ xbase = x + ((size_t)n * CC + cc0) * HW;
    float* __restrict__ f0 = feats + (((size_t)nk * 2 + 0) * CC + cc0) * nij;
    float* __restrict__ f1 = feats + (((size_t)nk * 2 + 1) * CC + cc0) * nij;

    if (tid < nv) {
        // ---- dense valid position: (i,j) = (tid/width, tid%width) ----
        const unsigned magic_w =
            (unsigned)((0x100000000ULL + (unsigned)width - 1) / (unsigned)width);
        const int i = (int)__umulhi((unsigned)tid, magic_w);
        const int j = tid - i * width;

        const int e0 = i * MW + j;                                // d=0 dest
        const int d1 = (PH - 1 - i) * MW + (width - 1 - j);       // d=1 dest

        float px, py;
        const float fi = (float)i, fj = (float)j;
        if (wide) {
            px = xmin + fj * bwf * inv_wf1;
            py = ymin + fi * bhf * inv_ph1;
        } else {
            px = xmin + fi * bwf * inv_ph1;
            py = ymin + (wf - fj) * bhf * inv_wf1;
        }
        const float ix = px - 0.5f;        // grid normalize/unnormalize cancels
        const float iy = py - 0.5f;
        const float x0f = floorf(ix), y0f = floorf(iy);
        const int x0 = (int)x0f, y0 = (int)y0f;
        const int x1 = x0 + 1,   y1 = y0 + 1;
        const float dx = ix - x0f, dy = iy - y0f;
        const float wx0 = 1.f - dx, wx1 = dx;
        const float wy0 = 1.f - dy, wy1 = dy;
        const bool vx0 = (x0 >= 0) & (x0 < WW);
        const bool vx1 = (x1 >= 0) & (x1 < WW);
        const bool vy0 = (y0 >= 0) & (y0 < HH);
        const bool vy1 = (y1 >= 0) & (y1 < HH);
        const float w00 = (vx0 & vy0) ? wx0 * wy0 : 0.f;
        const float w10 = (vx1 & vy0) ? wx1 * wy0 : 0.f;
        const float w01 = (vx0 & vy1) ? wx0 * wy1 : 0.f;
        const float w11 = (vx1 & vy1) ? wx1 * wy1 : 0.f;
        const int xc0 = min(max(x0, 0), WW - 1);
        const int xc1 = min(max(x1, 0), WW - 1);
        const int yc0 = min(max(y0, 0), HH - 1);
        const int yc1 = min(max(y1, 0), HH - 1);
        const int o00 = yc0 * WW + xc0;
        const int o10 = yc0 * WW + xc1;
        const int o01 = yc1 * WW + xc0;
        const int o11 = yc1 * WW + xc1;

        // Phase A: all gathers first (32 independent LDGs in flight)
        float v[CPB];
        #pragma unroll
        for (int c = 0; c < CPB; ++c) {
            const float* __restrict__ xc = xbase + (size_t)c * HW;
            v[c] = w00 * __ldg(xc + o00)
                 + w10 * __ldg(xc + o10)
                 + w01 * __ldg(xc + o01)
                 + w11 * __ldg(xc + o11);
        }

        // Phase B: all stores (coalesced forward / reverse-contiguous)
        #pragma unroll
        for (int c = 0; c < CPB; ++c) {
            __stwt(f0 + (size_t)c * nij + e0, v[c]);
            __stwt(f1 + (size_t)c * nij + d1, v[c]);
        }
    } else {
        // ---- padding fill: j in [width, MW), zero in BOTH planes ----
        const int P = MW - width;
        if (P > 0) {
            const int pt    = tid - nv;
            const int npad  = TPB - nv;
            const int total = PH * P;      // pad elems per plane-channel
            const unsigned magic_p =
                (unsigned)((0x100000000ULL + (unsigned)P - 1) / (unsigned)P);
            for (int e = pt; e < total; e += npad) {
                const int row = (int)__umulhi((unsigned)e, magic_p);
                const int jj  = e - row * P;
                const int off = row * MW + width + jj;
                #pragma unroll
                for (int c = 0; c < CPB; ++c) {
                    __stwt(f0 + (size_t)c * nij + off, 0.f);
                    __stwt(f1 + (size_t)c * nij + off, 0.f);
                }
            }
        }
    }
}

extern "C" void kernel_launch(void* const* d_in, const int* in_sizes, int n_in,
                              void* d_out, int out_size)
{
    const float* x     = (const float*)d_in[0];
    const float* boxes = (const float*)d_in[1];
    float* out = (float*)d_out;

    // out = concat(feats (N,K,2,C,PH,MW), widths (N,K,2))
    const long long widths_elems = (long long)NN * KK * 2;               // 1024
    const long long per_mw       = (long long)NN * KK * 2 * CC * PH;     // 1048576
    int MW = (int)(((long long)out_size - widths_elems) / per_mw);
    if (MW < 1) MW = 1;
    if (MW > 64) MW = 64;   // width <= 64 by construction (ratio < 8)

    float* feats  = out;
    float* widths = out + (size_t)per_mw * MW;

    dim3 grid(NN * KK, CC / CPB);
    bbp_kernel<<<grid, TPB>>>(x, boxes, feats, widths, MW);
}

// round 9
// speedup vs baseline: 1.4015x; 1.4015x over previous
#include <cuda_runtime.h>

#define PH   8
#define NN   8
#define KK   64
#define CC   128
#define HH   128
#define WW   128
#define HW   (HH * WW)

#define CPB   8                  // channels per block
#define TPB   256
#define RPT   2                  // positions per thread (nij <= 512)

// R3 structure (uniform per-warp work, one (n,k,d) pair of positions per
// thread) with channel-batched gathers: per position, all 8 channel values
// are gathered first (32 independent LDGs in flight), then all stores issue.

__global__ void __launch_bounds__(TPB)
bbp_kernel(const float* __restrict__ x,
           const float* __restrict__ boxes,
           float* __restrict__ feats,
           float* __restrict__ widths,
           int MW)
{
    const int nk  = blockIdx.x;            // n*KK + k
    const int n   = nk >> 6;
    const int cc0 = blockIdx.y * CPB;
    const int tid = threadIdx.x;

    // ---- box parameters (uniform per block) ----
    const float4 b = reinterpret_cast<const float4*>(boxes)[nk];
    const float xmin = b.x, ymin = b.y, xmax = b.z, ymax = b.w;
    const bool valid_box = !(xmin == 0.f && ymin == 0.f && xmax == 0.f && ymax == 0.f);
    const float bwf = valid_box ? (xmax - xmin) : 1.f;
    const float bhf = valid_box ? (ymax - ymin) : 1.f;
    const bool wide = bwf > bhf;
    const float ratio = wide ? (bwf / bhf) : (bhf / bwf);
    const int   width = valid_box ? (int)ceilf(ratio * (float)PH) : 0;
    const float wf    = (float)(width > 2 ? width : 2);
    const float inv_wf1 = 1.0f / (wf - 1.0f);
    const float inv_ph1 = 1.0f / (float)(PH - 1);

    const int nij = PH * MW;

    if (tid == 0 && blockIdx.y == 0) {
        widths[(size_t)nk * 2 + 0] = (float)width;
        widths[(size_t)nk * 2 + 1] = (float)width;
    }

    // exact floor(pos/MW) for pos < 512 via magic multiply
    const unsigned magic = (unsigned)((0x100000000ULL + (unsigned)MW - 1) / (unsigned)MW);

    const float* __restrict__ xbase = x + ((size_t)n * CC + cc0) * HW;
    float* __restrict__ f0 = feats + (((size_t)nk * 2 + 0) * CC + cc0) * nij;
    float* __restrict__ f1 = feats + (((size_t)nk * 2 + 1) * CC + cc0) * nij;

    #pragma unroll
    for (int r = 0; r < RPT; ++r) {
        const int e = tid + r * TPB;
        if (e >= nij) continue;

        const int i = (int)__umulhi((unsigned)e, magic);
        const int j = e - i * MW;
        const bool val = (j < width);

        int d1 = e;
        float v[CPB];

        if (val) {
            d1 = (PH - 1 - i) * MW + (width - 1 - j);

            float px, py;
            const float fi = (float)i, fj = (float)j;
            if (wide) {
                px = xmin + fj * bwf * inv_wf1;
                py = ymin + fi * bhf * inv_ph1;
            } else {
                px = xmin + fi * bwf * inv_ph1;
                py = ymin + (wf - fj) * bhf * inv_wf1;
            }
            const float ix = px - 0.5f;    // grid normalize/unnormalize cancels
            const float iy = py - 0.5f;
            const float x0f = floorf(ix), y0f = floorf(iy);
            const int x0 = (int)x0f, y0 = (int)y0f;
            const int x1 = x0 + 1,   y1 = y0 + 1;
            const float dx = ix - x0f, dy = iy - y0f;
            const float wx0 = 1.f - dx, wx1 = dx;
            const float wy0 = 1.f - dy, wy1 = dy;
            const bool vx0 = (x0 >= 0) & (x0 < WW);
            const bool vx1 = (x1 >= 0) & (x1 < WW);
            const bool vy0 = (y0 >= 0) & (y0 < HH);
            const bool vy1 = (y1 >= 0) & (y1 < HH);
            const float w00 = (vx0 & vy0) ? wx0 * wy0 : 0.f;
            const float w10 = (vx1 & vy0) ? wx1 * wy0 : 0.f;
            const float w01 = (vx0 & vy1) ? wx0 * wy1 : 0.f;
            const float w11 = (vx1 & vy1) ? wx1 * wy1 : 0.f;
            const int xc0 = min(max(x0, 0), WW - 1);
            const int xc1 = min(max(x1, 0), WW - 1);
            const int yc0 = min(max(y0, 0), HH - 1);
            const int yc1 = min(max(y1, 0), HH - 1);
            const int o00 = yc0 * WW + xc0;
            const int o10 = yc0 * WW + xc1;
            const int o01 = yc1 * WW + xc0;
            const int o11 = yc1 * WW + xc1;

            // gather ALL channels first: 32 independent LDGs in flight
            #pragma unroll
            for (int c = 0; c < CPB; ++c) {
                const float* __restrict__ xc = xbase + (size_t)c * HW;
                v[c] = w00 * __ldg(xc + o00)
                     + w10 * __ldg(xc + o10)
                     + w01 * __ldg(xc + o01)
                     + w11 * __ldg(xc + o11);
            }
        } else {
            #pragma unroll
            for (int c = 0; c < CPB; ++c) v[c] = 0.f;
        }

        // store phase: both planes (forward + flipped/self-pos-pad), coalesced
        #pragma unroll
        for (int c = 0; c < CPB; ++c) {
            __stwt(f0 + (size_t)c * nij + e,  v[c]);
            __stwt(f1 + (size_t)c * nij + d1, v[c]);
        }
    }
}

extern "C" void kernel_launch(void* const* d_in, const int* in_sizes, int n_in,
                              void* d_out, int out_size)
{
    const float* x     = (const float*)d_in[0];
    const float* boxes = (const float*)d_in[1];
    float* out = (float*)d_out;

    // out = concat(feats (N,K,2,C,PH,MW), widths (N,K,2))
    const long long widths_elems = (long long)NN * KK * 2;               // 1024
    const long long per_mw       = (long long)NN * KK * 2 * CC * PH;     // 1048576
    int MW = (int)(((long long)out_size - widths_elems) / per_mw);
    if (MW < 1) MW = 1;
    if (MW > 64) MW = 64;   // nij <= 512 by construction (ratio < 8)

    float* feats  = out;
    float* widths = out + (size_t)per_mw * MW;

    dim3 grid(NN * KK, CC / CPB);
    bbp_kernel<<<grid, TPB>>>(x, boxes, feats, widths, MW);
}

// round 10
// speedup vs baseline: 1.4706x; 1.0493x over previous
#include <cuda_runtime.h>

#define PH   8
#define NN   8
#define KK   64
#define CC   128
#define HH   128
#define WW   128
#define HW   (HH * WW)

#define CSPLIT 16                // channel chunks per (n,k) box
#define CPB   (CC / CSPLIT)      // 8 channels per block
#define TPB   512                // one (i,j) record per thread (nij <= 512)

// Champion R3 structure: one block = one (n,k) box, BOTH directions d=0/1,
// CPB channels; one position per thread, record in registers, all 8 channel
// gathers batched (32 independent LDGs) then 16 coalesced stores.
// Change vs R3: __stcs (evict-first streaming) instead of __stwt
// (write-through) so L2 coalesces output writebacks and x stays resident.

__global__ void __launch_bounds__(TPB)
bbp_kernel(const float* __restrict__ x,
           const float* __restrict__ boxes,
           float* __restrict__ feats,
           float* __restrict__ widths,
           int MW)
{
    const int nk  = blockIdx.x;            // n*KK + k
    const int n   = nk >> 6;
    const int cc0 = blockIdx.y * CPB;
    const int tid = threadIdx.x;

    // ---- box parameters (uniform per block) ----
    const float4 b = reinterpret_cast<const float4*>(boxes)[nk];
    const float xmin = b.x, ymin = b.y, xmax = b.z, ymax = b.w;
    const bool valid_box = !(xmin == 0.f && ymin == 0.f && xmax == 0.f && ymax == 0.f);
    const float bwf = valid_box ? (xmax - xmin) : 1.f;
    const float bhf = valid_box ? (ymax - ymin) : 1.f;
    const bool wide = bwf > bhf;
    const float ratio = wide ? (bwf / bhf) : (bhf / bwf);
    const int   width = valid_box ? (int)ceilf(ratio * (float)PH) : 0;
    const float wf    = (float)(width > 2 ? width : 2);
    const float inv_wf1 = 1.0f / (wf - 1.0f);
    const float inv_ph1 = 1.0f / (float)(PH - 1);

    const int nij = PH * MW;
    const int e   = tid;

    if (tid == 0 && blockIdx.y == 0) {
        widths[(size_t)nk * 2 + 0] = (float)width;
        widths[(size_t)nk * 2 + 1] = (float)width;
    }
    if (e >= nij) return;

    // exact floor(e/MW) for e < 512 via magic multiply
    const unsigned magic = (unsigned)((0x100000000ULL + (unsigned)MW - 1) / (unsigned)MW);
    const int i = (int)__umulhi((unsigned)e, magic);
    const int j = e - i * MW;
    const bool val = (j < width);

    int4   off = make_int4(0, 0, 0, 0);
    float4 w   = make_float4(0.f, 0.f, 0.f, 0.f);
    int    dst1 = e;

    if (val) {
        dst1 = (PH - 1 - i) * MW + (width - 1 - j);
        float px, py;
        const float fi = (float)i, fj = (float)j;
        if (wide) {
            px = xmin + fj * bwf * inv_wf1;
            py = ymin + fi * bhf * inv_ph1;
        } else {
            px = xmin + fi * bwf * inv_ph1;
            py = ymin + (wf - fj) * bhf * inv_wf1;
        }
        const float ix = px - 0.5f;   // grid normalize/unnormalize cancels exactly
        const float iy = py - 0.5f;
        const float x0f = floorf(ix), y0f = floorf(iy);
        const int x0 = (int)x0f, y0 = (int)y0f;
        const int x1 = x0 + 1,   y1 = y0 + 1;
        const float dx = ix - x0f, dy = iy - y0f;
        const float wx0 = 1.f - dx, wx1 = dx;
        const float wy0 = 1.f - dy, wy1 = dy;
        const bool vx0 = (x0 >= 0) & (x0 < WW);
        const bool vx1 = (x1 >= 0) & (x1 < WW);
        const bool vy0 = (y0 >= 0) & (y0 < HH);
        const bool vy1 = (y1 >= 0) & (y1 < HH);
        w.x = (vx0 & vy0) ? wx0 * wy0 : 0.f;
        w.y = (vx1 & vy0) ? wx1 * wy0 : 0.f;
        w.z = (vx0 & vy1) ? wx0 * wy1 : 0.f;
        w.w = (vx1 & vy1) ? wx1 * wy1 : 0.f;
        const int xc0 = min(max(x0, 0), WW - 1);
        const int xc1 = min(max(x1, 0), WW - 1);
        const int yc0 = min(max(y0, 0), HH - 1);
        const int yc1 = min(max(y1, 0), HH - 1);
        off.x = yc0 * WW + xc0;
        off.y = yc0 * WW + xc1;
        off.z = yc1 * WW + xc0;
        off.w = yc1 * WW + xc1;
    }

    // ---- gather phase: all channels first (32 independent LDGs in flight) ----
    const float* __restrict__ xbase = x + ((size_t)n * CC + cc0) * HW;
    float* __restrict__ out0 = feats + (((size_t)nk * 2 + 0) * CC + cc0) * nij + e;
    float* __restrict__ out1 = feats + (((size_t)nk * 2 + 1) * CC + cc0) * nij + dst1;

    float v[CPB];
    if (val) {
        #pragma unroll
        for (int c = 0; c < CPB; ++c) {
            const float* __restrict__ xc = xbase + (size_t)c * HW;
            v[c] = w.x * __ldg(xc + off.x)
                 + w.y * __ldg(xc + off.y)
                 + w.z * __ldg(xc + off.z)
                 + w.w * __ldg(xc + off.w);
        }
    } else {
        #pragma unroll
        for (int c = 0; c < CPB; ++c) v[c] = 0.f;
    }

    // ---- store phase: streaming evict-first, both planes coalesced ----
    #pragma unroll
    for (int c = 0; c < CPB; ++c) {
        __stcs(out0 + (size_t)c * nij, v[c]);   // straight
        __stcs(out1 + (size_t)c * nij, v[c]);   // flipped (or same-slot zero pad)
    }
}

extern "C" void kernel_launch(void* const* d_in, const int* in_sizes, int n_in,
                              void* d_out, int out_size)
{
    const float* x     = (const float*)d_in[0];
    const float* boxes = (const float*)d_in[1];
    float* out = (float*)d_out;

    // out = concat(feats (N,K,2,C,PH,MW), widths (N,K,2))
    const long long widths_elems = (long long)NN * KK * 2;               // 1024
    const long long per_mw       = (long long)NN * KK * 2 * CC * PH;     // 1048576
    int MW = (int)(((long long)out_size - widths_elems) / per_mw);
    if (MW < 1) MW = 1;
    if (MW > 64) MW = 64;   // nij <= 512 by construction (ratio < 8)

    float* feats  = out;
    float* widths = out + (size_t)per_mw * MW;

    dim3 grid(NN * KK, CSPLIT);
    bbp_kernel<<<grid, TPB>>>(x, boxes, feats, widths, MW);
}